// round 2
// baseline (speedup 1.0000x reference)
#include <cuda_runtime.h>
#include <cstdint>

#define BB 8
#define NN 512
#define KK 30
#define HAA 20
#define HP 22
#define EMB 484
#define KSZ 9
#define MAXM 30
#define NSLOT (BB*MAXM)      // 240
#define NSEQ 99              // sortcery rows (output S-1)
#define CIT 4356             // EMB*KSZ
#define CIQ 121              // EMB/4 ci-split

// ---------------- scratch (static device globals; no allocation) ----------------
__device__ float g_Wtf[CIT*EMB];     // [(ci*9+t)][c]
__device__ float g_Wta[CIT*EMB];
__device__ float g_W1t[EMB*EMB];     // [ci][c]
__device__ float g_W2t[EMB*EMB];
__device__ float g_linv[NSLOT*EMB];  // scattered rows (padded 22x22 layout)
__device__ float g_O[NSLOT*EMB];     // conv 'features' accumulator
__device__ float g_A[NSLOT*EMB];     // conv 'attention' accumulator
__device__ float g_LA[NSLOT*EMB];    // relu(la)
__device__ float g_Y1[NSLOT*EMB];    // MLP layer1 accumulator (init b1)
__device__ float g_DDG[(NSLOT+1)*EMB]; // ddg rows; row 240 = background
__device__ int   g_slot[BB*NN];      // dense pos -> slot (-1 if none)
__device__ int   g_m[BB];            // distinct scattered positions per batch
__device__ int   g_cntT[KSZ];        // conv pair count per tap
__device__ int   g_pairIn[KSZ*NSLOT];
__device__ int   g_pairOut[KSZ*NSLOT];

// ---------------- K0: transposes (+ zero tap counters) ----------------
__global__ void k_transpose(const float* __restrict__ Wf, const float* __restrict__ Wa,
                            const float* __restrict__ W1, const float* __restrict__ W2) {
    __shared__ float tile[32][33];
    int mid = blockIdx.z;
    const float* src; float* dst; int C;
    if      (mid == 0) { src = Wf; dst = g_Wtf; C = CIT; }
    else if (mid == 1) { src = Wa; dst = g_Wta; C = CIT; }
    else if (mid == 2) { src = W1; dst = g_W1t; C = EMB; }
    else               { src = W2; dst = g_W2t; C = EMB; }

    if (mid == 0 && blockIdx.x == 0 && blockIdx.y == 0 &&
        threadIdx.x == 0 && threadIdx.y == 0)
        for (int t = 0; t < KSZ; t++) g_cntT[t] = 0;

    int xBase = blockIdx.x * 32;
    if (xBase >= C) return;
    int yBase = blockIdx.y * 32;
    int x = xBase + threadIdx.x;
    for (int j = threadIdx.y; j < 32; j += 8) {
        int y = yBase + j;
        if (y < EMB && x < C) tile[j][threadIdx.x] = src[y * C + x];
    }
    __syncthreads();
    int ox = yBase + threadIdx.x;               // dest col (< EMB)
    for (int j = threadIdx.y; j < 32; j += 8) {
        int oy = xBase + j;                     // dest row (< C)
        if (oy < C && ox < EMB) dst[oy * EMB + ox] = tile[threadIdx.x][j];
    }
}

// ---------------- K1: scatter (last-wins dedup), pair lists, O/A init ----------------
__global__ void k_scatter(const float* __restrict__ etab, const int* __restrict__ E_idx,
                          const int* __restrict__ mut_pos,
                          const float* __restrict__ b_f, const float* __restrict__ b_a) {
    int b = blockIdx.x, tid = threadIdx.x;
    __shared__ int win[NN];
    __shared__ int sPos[MAXM], sSrc[MAXM];
    __shared__ int sM;
    win[tid] = -1;
    g_slot[b * NN + tid] = -1;
    __syncthreads();
    int mp = mut_pos[b];
    if (tid == 0) {
        const int* nb = &E_idx[(b * NN + mp) * KK];
        for (int j = 0; j < KK; j++) win[nb[j]] = j;   // later j overwrites: last wins
        int m = 0;
        for (int l = 0; l < NN; l++) {
            int w = win[l];
            if (w >= 0) { g_slot[b * NN + l] = m; sPos[m] = l; sSrc[m] = w; m++; }
        }
        sM = m; g_m[b] = m;
    }
    __syncthreads();
    int m = sM;
    if (tid < EMB) {
        int c = tid, h0 = c / HP, h1 = c % HP;
        float bf = b_f[c], ba = b_a[c];
        bool valid = (h0 < HAA) && (h1 < HAA);
        int srcc = h0 * HAA + h1;
        for (int s = 0; s < m; s++) {
            float v = 0.f;
            if (valid)
                v = etab[(size_t)((b * NN + mp) * KK + sSrc[s]) * (HAA * HAA) + srcc];
            int g = (b * MAXM + s) * EMB + c;
            g_linv[g] = v; g_O[g] = bf; g_A[g] = ba;
        }
    }
    if (tid == 0) {
        for (int s = 0; s < m; s++) {
            int l = sPos[s];
            for (int t = 0; t < KSZ; t++) {
                int p = l + t - 4;                       // y[l] += W[t] * x[l+t-4]
                if (p >= 0 && p < NN) {
                    int si = g_slot[b * NN + p];
                    if (si >= 0) {
                        int idx = atomicAdd(&g_cntT[t], 1);
                        g_pairIn[t * NSLOT + idx]  = b * MAXM + si;
                        g_pairOut[t * NSLOT + idx] = b * MAXM + s;
                    }
                }
            }
        }
    }
}

// ---------------- K2: conv as chunked GEMV-batches ----------------
__global__ void k_conv() {
    int t = blockIdx.y;
    int cnt = g_cntT[t];
    int p0 = blockIdx.x * 8;
    if (p0 >= cnt) return;
    int nb = min(8, cnt - p0);
    int ciBeg = blockIdx.z * CIQ;
    __shared__ float xs[8][CIQ];
    int tid = threadIdx.x;
    if (tid < CIQ) {
        for (int s = 0; s < 8; s++) {
            float v = 0.f;
            if (s < nb) {
                int gin = g_pairIn[t * NSLOT + p0 + s];
                v = g_linv[gin * EMB + ciBeg + tid];
            }
            xs[s][tid] = v;
        }
    }
    __syncthreads();
    int c = tid;
    if (c >= EMB) return;
    float ao[8] = {0,0,0,0,0,0,0,0};
    float aa[8] = {0,0,0,0,0,0,0,0};
    const float* wf = &g_Wtf[(ciBeg * KSZ + t) * EMB + c];
    const float* wa = &g_Wta[(ciBeg * KSZ + t) * EMB + c];
    #pragma unroll 2
    for (int ci = 0; ci < CIQ; ci++) {
        float wfv = wf[ci * (KSZ * EMB)];
        float wav = wa[ci * (KSZ * EMB)];
        #pragma unroll
        for (int s = 0; s < 8; s++) {
            float x = xs[s][ci];
            ao[s] += wfv * x;
            aa[s] += wav * x;
        }
    }
    for (int s = 0; s < nb; s++) {
        int go = g_pairOut[t * NSLOT + p0 + s];
        atomicAdd(&g_O[go * EMB + c], ao[s]);
        atomicAdd(&g_A[go * EMB + c], aa[s]);
    }
}

// ---------------- K3: masked softmax -> relu(la); init Y1/DDG ----------------
__global__ void k_softmax(const float* __restrict__ b1, const float* __restrict__ b2,
                          const float* __restrict__ wddg, const float* __restrict__ bddg) {
    int b = blockIdx.x, c = threadIdx.x;
    if (c >= EMB) return;
    int m = g_m[b];
    float b1c = b1[c];
    float dinit = b2[c] * wddg[0] + bddg[0];
    float mx = -3.4e38f;
    for (int s = 0; s < m; s++) mx = fmaxf(mx, g_A[(b * MAXM + s) * EMB + c]);
    float den = 0.f;
    for (int s = 0; s < m; s++) den += expf(g_A[(b * MAXM + s) * EMB + c] - mx);
    float inv = 1.f / den;
    for (int s = 0; s < m; s++) {
        int g = (b * MAXM + s) * EMB + c;
        float la = g_O[g] * (expf(g_A[g] - mx) * inv);
        g_LA[g] = fmaxf(la, 0.f);
    }
    for (int s = m; s < MAXM; s++) g_LA[(b * MAXM + s) * EMB + c] = 0.f;
    for (int s = 0; s < MAXM; s++) {
        g_Y1[(b * MAXM + s) * EMB + c] = b1c;
        g_DDG[(b * MAXM + s) * EMB + c] = dinit;
    }
    if (b == 0) g_DDG[NSLOT * EMB + c] = dinit;     // background row
}

// ---------------- K4: MLP layer 1 (chunked, ci-split, atomic accumulate) ----------------
__global__ void k_mlp1() {
    int g0 = blockIdx.x * 8;
    int ciBeg = blockIdx.y * CIQ;
    __shared__ float xs[8][CIQ];
    int tid = threadIdx.x;
    if (tid < CIQ)
        for (int s = 0; s < 8; s++)
            xs[s][tid] = g_LA[(g0 + s) * EMB + ciBeg + tid];
    __syncthreads();
    int c = tid;
    if (c >= EMB) return;
    float acc[8] = {0,0,0,0,0,0,0,0};
    #pragma unroll 2
    for (int ci = 0; ci < CIQ; ci++) {
        float w = g_W1t[(ciBeg + ci) * EMB + c];
        #pragma unroll
        for (int s = 0; s < 8; s++) acc[s] += w * xs[s][ci];
    }
    for (int s = 0; s < 8; s++) atomicAdd(&g_Y1[(g0 + s) * EMB + c], acc[s]);
}

// ---------------- K5: MLP layer 2 + ddg scale (incl. background row 240) ----------------
__global__ void k_mlp2(const float* __restrict__ b1, const float* __restrict__ wddg) {
    int g0 = blockIdx.x * 8;
    int ciBeg = blockIdx.y * CIQ;
    __shared__ float xs[8][CIQ];
    int tid = threadIdx.x;
    if (tid < CIQ) {
        for (int s = 0; s < 8; s++) {
            int g = g0 + s; float v = 0.f;
            if (g < NSLOT)          v = fmaxf(g_Y1[g * EMB + ciBeg + tid], 0.f);
            else if (g == NSLOT)    v = fmaxf(b1[ciBeg + tid], 0.f);   // bg: y1 = b1
            xs[s][tid] = v;
        }
    }
    __syncthreads();
    int c = tid;
    if (c >= EMB) return;
    float acc[8] = {0,0,0,0,0,0,0,0};
    #pragma unroll 2
    for (int ci = 0; ci < CIQ; ci++) {
        float w = g_W2t[(ciBeg + ci) * EMB + c];
        #pragma unroll
        for (int s = 0; s < 8; s++) acc[s] += w * xs[s][ci];
    }
    float wd = wddg[0];
    for (int s = 0; s < 8; s++) {
        int g = g0 + s;
        if (g <= NSLOT) atomicAdd(&g_DDG[g * EMB + c], wd * acc[s]);
    }
}

// ---------------- K6: scoring: out[b,s] = score(seq_s) - score(WT) ----------------
__global__ void k_score(const int* __restrict__ sortcery, const int* __restrict__ seqs,
                        const int* __restrict__ mut_pos, float* __restrict__ out) {
    int s = blockIdx.x, b = blockIdx.y, tid = threadIdx.x;
    int mp = mut_pos[b];
    int spos = sortcery[((size_t)(b * NSEQ + s)) * NN + mp];
    int wpos = seqs[b * NN + mp];
    float part = 0.f;
    for (int j = tid; j < NN; j += 128) {
        int slot = g_slot[b * NN + j];
        int row = (slot >= 0) ? (b * MAXM + slot) : NSLOT;
        int as = sortcery[((size_t)(b * NSEQ + s)) * NN + j];
        int aw = seqs[b * NN + j];
        part += g_DDG[row * EMB + spos * HP + as]
              - g_DDG[row * EMB + wpos * HP + aw];
    }
    __shared__ float red[128];
    red[tid] = part;
    __syncthreads();
    for (int off = 64; off > 0; off >>= 1) {
        if (tid < off) red[tid] += red[tid + off];
        __syncthreads();
    }
    if (tid == 0) out[b * NSEQ + s] = red[0];
}

// ---------------- launch ----------------
extern "C" void kernel_launch(void* const* d_in, const int* in_sizes, int n_in,
                              void* d_out, int out_size) {
    const float* etab     = (const float*)d_in[0];
    const int*   E_idx    = (const int*)  d_in[1];
    const int*   sortcery = (const int*)  d_in[2];
    const int*   seqs     = (const int*)  d_in[3];
    const int*   mut_pos  = (const int*)  d_in[4];
    const float* Wf       = (const float*)d_in[6];
    const float* bf       = (const float*)d_in[7];
    const float* Wa       = (const float*)d_in[8];
    const float* ba       = (const float*)d_in[9];
    const float* W1       = (const float*)d_in[10];
    const float* b1       = (const float*)d_in[11];
    const float* W2       = (const float*)d_in[12];
    const float* b2       = (const float*)d_in[13];
    const float* wddg     = (const float*)d_in[14];
    const float* bddg     = (const float*)d_in[15];
    float* out = (float*)d_out;

    k_transpose<<<dim3(137, 16, 4), dim3(32, 8)>>>(Wf, Wa, W1, W2);
    k_scatter<<<BB, 512>>>(etab, E_idx, mut_pos, bf, ba);
    k_conv<<<dim3(30, KSZ, 4), 512>>>();
    k_softmax<<<BB, 512>>>(b1, b2, wddg, bddg);
    k_mlp1<<<dim3(30, 4), 512>>>();
    k_mlp2<<<dim3(31, 4), 512>>>(b1, wddg);
    k_score<<<dim3(NSEQ, BB), 128>>>(sortcery, seqs, mut_pos, out);
}

// round 3
// speedup vs baseline: 1.5473x; 1.5473x over previous
#include <cuda_runtime.h>
#include <cstdint>

#define BB 8
#define NN 512
#define KK 30
#define HAA 20
#define HP 22
#define EMB 484
#define KSZ 9
#define MAXM 30
#define NSLOT (BB*MAXM)      // 240
#define NSEQ 99
#define CIT 4356             // EMB*KSZ
#define CIQ 121              // EMB/4 ci-split

// ---------------- scratch (static device globals; no allocation) ----------------
__device__ float g_Wtf[CIT*EMB];     // [(ci*9+t)][c]
__device__ float g_Wta[CIT*EMB];
__device__ float g_W1t[EMB*EMB];     // [ci][c]
__device__ float g_W2t[EMB*EMB];
__device__ float g_linv[NSLOT*EMB];
__device__ float g_O[NSLOT*EMB];
__device__ float g_A[NSLOT*EMB];
__device__ float g_LA[NSLOT*EMB];
__device__ float g_Y1[NSLOT*EMB];
__device__ float g_DDG[(NSLOT+1)*EMB];
__device__ int   g_slot[BB*NN];
__device__ int   g_m[BB];
__device__ int   g_cntBT[BB*KSZ];          // per-(b,tap) pair count
__device__ int   g_pairIn[BB*KSZ*MAXM];
__device__ int   g_pairOut[BB*KSZ*MAXM];

// ---------------- K1 fused: transposes + parallel scatter ----------------
// transpose block counts: mid0/1 (C=4356): 137*16=2192 each; mid2/3 (C=484): 16*16=256 each
#define TB0 2192
#define TB1 4384
#define TB2 4640
#define TB3 4896
#define PREP_BLOCKS (TB3 + BB)

__global__ void k_prep(const float* __restrict__ Wf, const float* __restrict__ Wa,
                       const float* __restrict__ W1, const float* __restrict__ W2,
                       const float* __restrict__ etab, const int* __restrict__ E_idx,
                       const int* __restrict__ mut_pos,
                       const float* __restrict__ b_f, const float* __restrict__ b_a) {
    int bx = blockIdx.x;
    int tid = threadIdx.x;

    if (bx < TB3) {
        // ---- transpose part (256 threads as 32x8 tile workers) ----
        __shared__ float tile[32][33];
        const float* src; float* dst; int C, xt, yt;
        if (bx < TB0)      { src = Wf; dst = g_Wtf; C = CIT; int i = bx;       xt = i % 137; yt = i / 137; }
        else if (bx < TB1) { src = Wa; dst = g_Wta; C = CIT; int i = bx - TB0; xt = i % 137; yt = i / 137; }
        else if (bx < TB2) { src = W1; dst = g_W1t; C = EMB; int i = bx - TB1; xt = i % 16;  yt = i / 16; }
        else               { src = W2; dst = g_W2t; C = EMB; int i = bx - TB2; xt = i % 16;  yt = i / 16; }
        int tx = tid & 31, ty = tid >> 5;
        int xBase = xt * 32, yBase = yt * 32;
        int x = xBase + tx;
        for (int j = ty; j < 32; j += 8) {
            int y = yBase + j;
            if (y < EMB && x < C) tile[j][tx] = src[y * C + x];
        }
        __syncthreads();
        int ox = yBase + tx;
        for (int j = ty; j < 32; j += 8) {
            int oy = xBase + j;
            if (oy < C && ox < EMB) dst[oy * EMB + ox] = tile[tx][j];
        }
        return;
    }

    // ---- scatter part (256 threads, one block per batch) ----
    int b = bx - TB3;
    __shared__ int win[NN];
    __shared__ int slotArr[NN];
    __shared__ unsigned msk[16];
    __shared__ int cpre[16];
    __shared__ int sPos[MAXM], sSrc[MAXM];
    __shared__ int sM;

    win[tid] = -1; win[tid + 256] = -1;
    if (tid < KSZ) g_cntBT[b * KSZ + tid] = 0;
    __syncthreads();

    int mp = mut_pos[b];
    const int* nb = &E_idx[(b * NN + mp) * KK];
    if (tid < KK) atomicMax(&win[nb[tid]], tid);   // last j wins == max j wins
    __syncthreads();

    int warp = tid >> 5, lane = tid & 31;
    #pragma unroll
    for (int h = 0; h < 2; h++) {
        int chunk = warp + h * 8;
        int l = chunk * 32 + lane;
        unsigned bal = __ballot_sync(0xffffffffu, win[l] >= 0);
        if (lane == 0) msk[chunk] = bal;
    }
    __syncthreads();
    if (tid == 0) {
        int acc = 0;
        for (int i = 0; i < 16; i++) { cpre[i] = acc; acc += __popc(msk[i]); }
        sM = acc; g_m[b] = acc;
    }
    __syncthreads();
    #pragma unroll
    for (int h = 0; h < 2; h++) {
        int chunk = warp + h * 8;
        int l = chunk * 32 + lane;
        int w = win[l];
        int slot = -1;
        if (w >= 0) {
            slot = cpre[chunk] + __popc(msk[chunk] & ((1u << lane) - 1));
            sPos[slot] = l; sSrc[slot] = w;
        }
        slotArr[l] = slot;
        g_slot[b * NN + l] = slot;
    }
    __syncthreads();

    int m = sM;
    // data copy: scattered rows (padded 22x22), init O/A with biases
    for (int c = tid; c < EMB; c += 256) {
        int h0 = c / HP, h1 = c % HP;
        float bfv = b_f[c], bav = b_a[c];
        bool valid = (h0 < HAA) && (h1 < HAA);
        int srcc = h0 * HAA + h1;
        for (int s = 0; s < m; s++) {
            float v = 0.f;
            if (valid)
                v = etab[(size_t)((b * NN + mp) * KK + sSrc[s]) * (HAA * HAA) + srcc];
            int g = (b * MAXM + s) * EMB + c;
            g_linv[g] = v; g_O[g] = bfv; g_A[g] = bav;
        }
    }
    // pair lists, per (b,tap)
    for (int q = tid; q < m * KSZ; q += 256) {
        int s = q / KSZ, t = q % KSZ;
        int p = sPos[s] + t - 4;              // y[l] += W[t] * x[l+t-4]
        if (p >= 0 && p < NN) {
            int si = slotArr[p];
            if (si >= 0) {
                int idx = atomicAdd(&g_cntBT[b * KSZ + t], 1);
                g_pairIn[(b * KSZ + t) * MAXM + idx]  = b * MAXM + si;
                g_pairOut[(b * KSZ + t) * MAXM + idx] = b * MAXM + s;
            }
        }
    }
}

// ---------------- K2: conv as chunked GEMV-batches (per-b pair lists) ----------------
__global__ void k_conv() {
    int b = blockIdx.x >> 2;
    int p0 = (blockIdx.x & 3) * 8;
    int t = blockIdx.y;
    int cnt = g_cntBT[b * KSZ + t];
    if (p0 >= cnt) return;
    int nb = min(8, cnt - p0);
    int ciBeg = blockIdx.z * CIQ;
    __shared__ float xs[8][CIQ];
    int tid = threadIdx.x;
    if (tid < CIQ) {
        for (int s = 0; s < 8; s++) {
            float v = 0.f;
            if (s < nb) {
                int gin = g_pairIn[(b * KSZ + t) * MAXM + p0 + s];
                v = g_linv[gin * EMB + ciBeg + tid];
            }
            xs[s][tid] = v;
        }
    }
    __syncthreads();
    int c = tid;
    if (c >= EMB) return;
    float ao[8] = {0,0,0,0,0,0,0,0};
    float aa[8] = {0,0,0,0,0,0,0,0};
    const float* wf = &g_Wtf[(ciBeg * KSZ + t) * EMB + c];
    const float* wa = &g_Wta[(ciBeg * KSZ + t) * EMB + c];
    #pragma unroll 2
    for (int ci = 0; ci < CIQ; ci++) {
        float wfv = wf[ci * (KSZ * EMB)];
        float wav = wa[ci * (KSZ * EMB)];
        #pragma unroll
        for (int s = 0; s < 8; s++) {
            float x = xs[s][ci];
            ao[s] += wfv * x;
            aa[s] += wav * x;
        }
    }
    for (int s = 0; s < nb; s++) {
        int go = g_pairOut[(b * KSZ + t) * MAXM + p0 + s];
        atomicAdd(&g_O[go * EMB + c], ao[s]);
        atomicAdd(&g_A[go * EMB + c], aa[s]);
    }
}

// ---------------- K3: register-resident masked softmax -> relu(la); init Y1/DDG ----------------
__global__ void k_softmax(const float* __restrict__ b1, const float* __restrict__ b2,
                          const float* __restrict__ wddg, const float* __restrict__ bddg) {
    int b = blockIdx.x;
    int c = blockIdx.y * 128 + threadIdx.x;
    if (c >= EMB) return;
    int m = g_m[b];
    int base = b * MAXM * EMB + c;
    float Av[MAXM], Ov[MAXM];
    #pragma unroll
    for (int s = 0; s < MAXM; s++) {
        Av[s] = (s < m) ? g_A[base + s * EMB] : -3.4e38f;
        Ov[s] = (s < m) ? g_O[base + s * EMB] : 0.f;
    }
    float mx = Av[0];
    #pragma unroll
    for (int s = 1; s < MAXM; s++) mx = fmaxf(mx, Av[s]);
    float den = 0.f;
    #pragma unroll
    for (int s = 0; s < MAXM; s++) { Av[s] = expf(Av[s] - mx); den += Av[s]; }
    float inv = 1.f / den;
    float b1c = b1[c];
    float dinit = b2[c] * wddg[0] + bddg[0];
    #pragma unroll
    for (int s = 0; s < MAXM; s++) {
        float la = (s < m) ? fmaxf(Ov[s] * (Av[s] * inv), 0.f) : 0.f;
        g_LA[base + s * EMB] = la;
        g_Y1[base + s * EMB] = b1c;
        g_DDG[base + s * EMB] = dinit;
    }
    if (b == 0) g_DDG[NSLOT * EMB + c] = dinit;   // background row
}

// ---------------- K4: MLP layer 1 ----------------
__global__ void k_mlp1() {
    int g0 = blockIdx.x * 8;
    int ciBeg = blockIdx.y * CIQ;
    __shared__ float xs[8][CIQ];
    int tid = threadIdx.x;
    if (tid < CIQ)
        for (int s = 0; s < 8; s++)
            xs[s][tid] = g_LA[(g0 + s) * EMB + ciBeg + tid];
    __syncthreads();
    int c = tid;
    if (c >= EMB) return;
    float acc[8] = {0,0,0,0,0,0,0,0};
    #pragma unroll 2
    for (int ci = 0; ci < CIQ; ci++) {
        float w = g_W1t[(ciBeg + ci) * EMB + c];
        #pragma unroll
        for (int s = 0; s < 8; s++) acc[s] += w * xs[s][ci];
    }
    for (int s = 0; s < 8; s++) atomicAdd(&g_Y1[(g0 + s) * EMB + c], acc[s]);
}

// ---------------- K5: MLP layer 2 + ddg scale (incl. background row 240) ----------------
__global__ void k_mlp2(const float* __restrict__ b1, const float* __restrict__ wddg) {
    int g0 = blockIdx.x * 8;
    int ciBeg = blockIdx.y * CIQ;
    __shared__ float xs[8][CIQ];
    int tid = threadIdx.x;
    if (tid < CIQ) {
        for (int s = 0; s < 8; s++) {
            int g = g0 + s; float v = 0.f;
            if (g < NSLOT)       v = fmaxf(g_Y1[g * EMB + ciBeg + tid], 0.f);
            else if (g == NSLOT) v = fmaxf(b1[ciBeg + tid], 0.f);    // bg: y1 = b1
            xs[s][tid] = v;
        }
    }
    __syncthreads();
    int c = tid;
    if (c >= EMB) return;
    float acc[8] = {0,0,0,0,0,0,0,0};
    #pragma unroll 2
    for (int ci = 0; ci < CIQ; ci++) {
        float w = g_W2t[(ciBeg + ci) * EMB + c];
        #pragma unroll
        for (int s = 0; s < 8; s++) acc[s] += w * xs[s][ci];
    }
    float wd = wddg[0];
    for (int s = 0; s < 8; s++) {
        int g = g0 + s;
        if (g <= NSLOT) atomicAdd(&g_DDG[g * EMB + c], wd * acc[s]);
    }
}

// ---------------- K6: scoring ----------------
__global__ void k_score(const int* __restrict__ sortcery, const int* __restrict__ seqs,
                        const int* __restrict__ mut_pos, float* __restrict__ out) {
    int s = blockIdx.x, b = blockIdx.y, tid = threadIdx.x;
    int mp = mut_pos[b];
    int spos = sortcery[((size_t)(b * NSEQ + s)) * NN + mp];
    int wpos = seqs[b * NN + mp];
    float part = 0.f;
    for (int j = tid; j < NN; j += 128) {
        int slot = g_slot[b * NN + j];
        int row = (slot >= 0) ? (b * MAXM + slot) : NSLOT;
        int as = sortcery[((size_t)(b * NSEQ + s)) * NN + j];
        int aw = seqs[b * NN + j];
        part += g_DDG[row * EMB + spos * HP + as]
              - g_DDG[row * EMB + wpos * HP + aw];
    }
    __shared__ float red[128];
    red[tid] = part;
    __syncthreads();
    for (int off = 64; off > 0; off >>= 1) {
        if (tid < off) red[tid] += red[tid + off];
        __syncthreads();
    }
    if (tid == 0) out[b * NSEQ + s] = red[0];
}

// ---------------- launch ----------------
extern "C" void kernel_launch(void* const* d_in, const int* in_sizes, int n_in,
                              void* d_out, int out_size) {
    const float* etab     = (const float*)d_in[0];
    const int*   E_idx    = (const int*)  d_in[1];
    const int*   sortcery = (const int*)  d_in[2];
    const int*   seqs     = (const int*)  d_in[3];
    const int*   mut_pos  = (const int*)  d_in[4];
    const float* Wf       = (const float*)d_in[6];
    const float* bf       = (const float*)d_in[7];
    const float* Wa       = (const float*)d_in[8];
    const float* ba       = (const float*)d_in[9];
    const float* W1       = (const float*)d_in[10];
    const float* b1       = (const float*)d_in[11];
    const float* W2       = (const float*)d_in[12];
    const float* b2       = (const float*)d_in[13];
    const float* wddg     = (const float*)d_in[14];
    const float* bddg     = (const float*)d_in[15];
    float* out = (float*)d_out;

    k_prep<<<PREP_BLOCKS, 256>>>(Wf, Wa, W1, W2, etab, E_idx, mut_pos, bf, ba);
    k_conv<<<dim3(32, KSZ, 4), 512>>>();
    k_softmax<<<dim3(BB, 4), 128>>>(b1, b2, wddg, bddg);
    k_mlp1<<<dim3(30, 4), 512>>>();
    k_mlp2<<<dim3(31, 4), 512>>>(b1, wddg);
    k_score<<<dim3(NSEQ, BB), 128>>>(sortcery, seqs, mut_pos, out);
}

// round 4
// speedup vs baseline: 2.2508x; 1.4546x over previous
#include <cuda_runtime.h>
#include <cstdint>

#define BB 8
#define NN 512
#define KK 30
#define HAA 20
#define HP 22
#define EMB 484
#define KSZ 9
#define MAXM 30
#define NSLOT (BB*MAXM)      // 240
#define NSEQ 99
#define CIT 4356             // EMB*KSZ
#define CIC 44               // ci chunk
#define NCH 11               // 484/44 chunks

// ---------------- scratch (static device globals; no allocation) ----------------
__device__ float g_Wtf[CIT*EMB];     // [(ci*9+t)][c]
__device__ float g_Wta[CIT*EMB];
__device__ float g_W1t[EMB*EMB];     // [ci][c]
__device__ float g_W2t[EMB*EMB];
__device__ float g_linv[NSLOT*EMB];
__device__ float g_O[NSLOT*EMB];
__device__ float g_A[NSLOT*EMB];
__device__ float g_LA[NSLOT*EMB];
__device__ float g_Y1[NSLOT*EMB];
__device__ float g_DDG[(NSLOT+1)*EMB];
__device__ int   g_slot[BB*NN];
__device__ int   g_m[BB];
__device__ int   g_cntBT[BB*KSZ];          // per-(b,tap) pair count
__device__ int   g_pairIn[BB*KSZ*MAXM];
__device__ int   g_pairOut[BB*KSZ*MAXM];

// ---------------- K1 fused: transposes + parallel scatter + Y1/DDG init ----------------
#define TB0 2192
#define TB1 4384
#define TB2 4640
#define TB3 4896
#define SCAT_END (TB3 + BB)
#define INIT_END (SCAT_END + NSLOT + 1)    // 241 init blocks
#define PREP_BLOCKS INIT_END

__global__ void k_prep(const float* __restrict__ Wf, const float* __restrict__ Wa,
                       const float* __restrict__ W1, const float* __restrict__ W2,
                       const float* __restrict__ etab, const int* __restrict__ E_idx,
                       const int* __restrict__ mut_pos,
                       const float* __restrict__ b_f, const float* __restrict__ b_a,
                       const float* __restrict__ b1, const float* __restrict__ b2,
                       const float* __restrict__ wddg, const float* __restrict__ bddg) {
    int bx = blockIdx.x;
    int tid = threadIdx.x;

    if (bx >= SCAT_END) {
        // ---- Y1 / DDG bias init (row = bx - SCAT_END; row 240 = background DDG) ----
        int row = bx - SCAT_END;
        float wd = wddg[0], bd = bddg[0];
        for (int c = tid; c < EMB; c += 256) {
            float dinit = b2[c] * wd + bd;
            g_DDG[row * EMB + c] = dinit;
            if (row < NSLOT) g_Y1[row * EMB + c] = b1[c];
        }
        return;
    }

    if (bx < TB3) {
        // ---- transpose part (256 threads as 32x8 tile workers) ----
        __shared__ float tile[32][33];
        const float* src; float* dst; int C, xt, yt;
        if (bx < TB0)      { src = Wf; dst = g_Wtf; C = CIT; int i = bx;       xt = i % 137; yt = i / 137; }
        else if (bx < TB1) { src = Wa; dst = g_Wta; C = CIT; int i = bx - TB0; xt = i % 137; yt = i / 137; }
        else if (bx < TB2) { src = W1; dst = g_W1t; C = EMB; int i = bx - TB1; xt = i % 16;  yt = i / 16; }
        else               { src = W2; dst = g_W2t; C = EMB; int i = bx - TB2; xt = i % 16;  yt = i / 16; }
        int tx = tid & 31, ty = tid >> 5;
        int xBase = xt * 32, yBase = yt * 32;
        int x = xBase + tx;
        for (int j = ty; j < 32; j += 8) {
            int y = yBase + j;
            if (y < EMB && x < C) tile[j][tx] = src[y * C + x];
        }
        __syncthreads();
        int ox = yBase + tx;
        for (int j = ty; j < 32; j += 8) {
            int oy = xBase + j;
            if (oy < C && ox < EMB) dst[oy * EMB + ox] = tile[tx][j];
        }
        return;
    }

    // ---- scatter part (256 threads, one block per batch) ----
    int b = bx - TB3;
    __shared__ int win[NN];
    __shared__ int slotArr[NN];
    __shared__ unsigned msk[16];
    __shared__ int cpre[16];
    __shared__ int sPos[MAXM], sSrc[MAXM];
    __shared__ int sM;

    win[tid] = -1; win[tid + 256] = -1;
    if (tid < KSZ) g_cntBT[b * KSZ + tid] = 0;
    __syncthreads();

    int mp = mut_pos[b];
    const int* nb = &E_idx[(b * NN + mp) * KK];
    if (tid < KK) atomicMax(&win[nb[tid]], tid);   // last j wins == max j wins
    __syncthreads();

    int warp = tid >> 5, lane = tid & 31;
    #pragma unroll
    for (int h = 0; h < 2; h++) {
        int chunk = warp + h * 8;
        int l = chunk * 32 + lane;
        unsigned bal = __ballot_sync(0xffffffffu, win[l] >= 0);
        if (lane == 0) msk[chunk] = bal;
    }
    __syncthreads();
    if (tid == 0) {
        int acc = 0;
        for (int i = 0; i < 16; i++) { cpre[i] = acc; acc += __popc(msk[i]); }
        sM = acc; g_m[b] = acc;
    }
    __syncthreads();
    #pragma unroll
    for (int h = 0; h < 2; h++) {
        int chunk = warp + h * 8;
        int l = chunk * 32 + lane;
        int w = win[l];
        int slot = -1;
        if (w >= 0) {
            slot = cpre[chunk] + __popc(msk[chunk] & ((1u << lane) - 1));
            sPos[slot] = l; sSrc[slot] = w;
        }
        slotArr[l] = slot;
        g_slot[b * NN + l] = slot;
    }
    __syncthreads();

    int m = sM;
    // data copy: scattered rows (padded 22x22), init O/A with biases
    for (int c = tid; c < EMB; c += 256) {
        int h0 = c / HP, h1 = c % HP;
        float bfv = b_f[c], bav = b_a[c];
        bool valid = (h0 < HAA) && (h1 < HAA);
        int srcc = h0 * HAA + h1;
        for (int s = 0; s < m; s++) {
            float v = 0.f;
            if (valid)
                v = etab[(size_t)((b * NN + mp) * KK + sSrc[s]) * (HAA * HAA) + srcc];
            int g = (b * MAXM + s) * EMB + c;
            g_linv[g] = v; g_O[g] = bfv; g_A[g] = bav;
        }
    }
    // pair lists, per (b,tap)
    for (int q = tid; q < m * KSZ; q += 256) {
        int s = q / KSZ, t = q % KSZ;
        int p = sPos[s] + t - 4;              // y[l] += W[t] * x[l+t-4]
        if (p >= 0 && p < NN) {
            int si = slotArr[p];
            if (si >= 0) {
                int idx = atomicAdd(&g_cntBT[b * KSZ + t], 1);
                g_pairIn[(b * KSZ + t) * MAXM + idx]  = b * MAXM + si;
                g_pairOut[(b * KSZ + t) * MAXM + idx] = b * MAXM + s;
            }
        }
    }
}

// ---------------- K2: conv as chunked GEMV-batches (44-ci chunks, 4x batched loads) ----------------
__global__ void k_conv() {
    int b = blockIdx.x >> 2;
    int p0 = (blockIdx.x & 3) * 8;
    int t = blockIdx.y;
    int cnt = g_cntBT[b * KSZ + t];
    if (p0 >= cnt) return;
    int nb = min(8, cnt - p0);
    int ciBeg = blockIdx.z * CIC;
    __shared__ float xs[8][CIC];
    int tid = threadIdx.x;
    if (tid < 8 * CIC) {
        int s = tid / CIC, i = tid % CIC;
        float v = 0.f;
        if (s < nb) {
            int gin = g_pairIn[(b * KSZ + t) * MAXM + p0 + s];
            v = g_linv[gin * EMB + ciBeg + i];
        }
        xs[s][i] = v;
    }
    __syncthreads();
    int c = tid;
    if (c >= EMB) return;
    float ao[8] = {0,0,0,0,0,0,0,0};
    float aa[8] = {0,0,0,0,0,0,0,0};
    const float* wf = &g_Wtf[(ciBeg * KSZ + t) * EMB + c];
    const float* wa = &g_Wta[(ciBeg * KSZ + t) * EMB + c];
    for (int cc = 0; cc < CIC; cc += 4) {
        float wfv[4], wav[4];
        #pragma unroll
        for (int k = 0; k < 4; k++) {
            wfv[k] = wf[(cc + k) * (KSZ * EMB)];
            wav[k] = wa[(cc + k) * (KSZ * EMB)];
        }
        #pragma unroll
        for (int k = 0; k < 4; k++)
            #pragma unroll
            for (int s = 0; s < 8; s++) {
                float x = xs[s][cc + k];
                ao[s] += wfv[k] * x;
                aa[s] += wav[k] * x;
            }
    }
    for (int s = 0; s < nb; s++) {
        int go = g_pairOut[(b * KSZ + t) * MAXM + p0 + s];
        atomicAdd(&g_O[go * EMB + c], ao[s]);
        atomicAdd(&g_A[go * EMB + c], aa[s]);
    }
}

// ---------------- K3: register-resident masked softmax -> relu(la) ----------------
__global__ void k_softmax() {
    int b = blockIdx.x;
    int c = blockIdx.y * 128 + threadIdx.x;
    if (c >= EMB) return;
    int m = g_m[b];
    int base = b * MAXM * EMB + c;
    float Av[MAXM], Ov[MAXM];
    #pragma unroll
    for (int s = 0; s < MAXM; s++) {
        Av[s] = (s < m) ? g_A[base + s * EMB] : -3.4e38f;
        Ov[s] = (s < m) ? g_O[base + s * EMB] : 0.f;
    }
    float mx = Av[0];
    #pragma unroll
    for (int s = 1; s < MAXM; s++) mx = fmaxf(mx, Av[s]);
    float den = 0.f;
    #pragma unroll
    for (int s = 0; s < MAXM; s++) { Av[s] = expf(Av[s] - mx); den += Av[s]; }
    float inv = 1.f / den;
    #pragma unroll
    for (int s = 0; s < MAXM; s++) {
        float la = (s < m) ? fmaxf(Ov[s] * (Av[s] * inv), 0.f) : 0.f;
        g_LA[base + s * EMB] = la;
    }
}

// ---------------- K4: MLP layer 1 ----------------
__global__ void k_mlp1() {
    int g0 = blockIdx.x * 8;
    int ciBeg = blockIdx.y * CIC;
    __shared__ float xs[8][CIC];
    int tid = threadIdx.x;
    if (tid < 8 * CIC) {
        int s = tid / CIC, i = tid % CIC;
        xs[s][i] = g_LA[(g0 + s) * EMB + ciBeg + i];
    }
    __syncthreads();
    int c = tid;
    if (c >= EMB) return;
    float acc[8] = {0,0,0,0,0,0,0,0};
    const float* wp = &g_W1t[ciBeg * EMB + c];
    for (int cc = 0; cc < CIC; cc += 4) {
        float wv[4];
        #pragma unroll
        for (int k = 0; k < 4; k++) wv[k] = wp[(cc + k) * EMB];
        #pragma unroll
        for (int k = 0; k < 4; k++)
            #pragma unroll
            for (int s = 0; s < 8; s++) acc[s] += wv[k] * xs[s][cc + k];
    }
    for (int s = 0; s < 8; s++) atomicAdd(&g_Y1[(g0 + s) * EMB + c], acc[s]);
}

// ---------------- K5: MLP layer 2 + ddg scale (incl. background row 240) ----------------
__global__ void k_mlp2(const float* __restrict__ b1, const float* __restrict__ wddg) {
    int g0 = blockIdx.x * 8;
    int ciBeg = blockIdx.y * CIC;
    __shared__ float xs[8][CIC];
    int tid = threadIdx.x;
    if (tid < 8 * CIC) {
        int s = tid / CIC, i = tid % CIC;
        int g = g0 + s; float v = 0.f;
        if (g < NSLOT)       v = fmaxf(g_Y1[g * EMB + ciBeg + i], 0.f);
        else if (g == NSLOT) v = fmaxf(b1[ciBeg + i], 0.f);    // bg: y1 = b1
        xs[s][i] = v;
    }
    __syncthreads();
    int c = tid;
    if (c >= EMB) return;
    float acc[8] = {0,0,0,0,0,0,0,0};
    const float* wp = &g_W2t[ciBeg * EMB + c];
    for (int cc = 0; cc < CIC; cc += 4) {
        float wv[4];
        #pragma unroll
        for (int k = 0; k < 4; k++) wv[k] = wp[(cc + k) * EMB];
        #pragma unroll
        for (int k = 0; k < 4; k++)
            #pragma unroll
            for (int s = 0; s < 8; s++) acc[s] += wv[k] * xs[s][cc + k];
    }
    float wd = wddg[0];
    for (int s = 0; s < 8; s++) {
        int g = g0 + s;
        if (g <= NSLOT) atomicAdd(&g_DDG[g * EMB + c], wd * acc[s]);
    }
}

// ---------------- K6: scoring ----------------
__global__ void k_score(const int* __restrict__ sortcery, const int* __restrict__ seqs,
                        const int* __restrict__ mut_pos, float* __restrict__ out) {
    int s = blockIdx.x, b = blockIdx.y, tid = threadIdx.x;
    int mp = mut_pos[b];
    int spos = sortcery[((size_t)(b * NSEQ + s)) * NN + mp];
    int wpos = seqs[b * NN + mp];
    float part = 0.f;
    for (int j = tid; j < NN; j += 128) {
        int slot = g_slot[b * NN + j];
        int row = (slot >= 0) ? (b * MAXM + slot) : NSLOT;
        int as = sortcery[((size_t)(b * NSEQ + s)) * NN + j];
        int aw = seqs[b * NN + j];
        part += g_DDG[row * EMB + spos * HP + as]
              - g_DDG[row * EMB + wpos * HP + aw];
    }
    __shared__ float red[128];
    red[tid] = part;
    __syncthreads();
    for (int off = 64; off > 0; off >>= 1) {
        if (tid < off) red[tid] += red[tid + off];
        __syncthreads();
    }
    if (tid == 0) out[b * NSEQ + s] = red[0];
}

// ---------------- launch ----------------
extern "C" void kernel_launch(void* const* d_in, const int* in_sizes, int n_in,
                              void* d_out, int out_size) {
    const float* etab     = (const float*)d_in[0];
    const int*   E_idx    = (const int*)  d_in[1];
    const int*   sortcery = (const int*)  d_in[2];
    const int*   seqs     = (const int*)  d_in[3];
    const int*   mut_pos  = (const int*)  d_in[4];
    const float* Wf       = (const float*)d_in[6];
    const float* bf       = (const float*)d_in[7];
    const float* Wa       = (const float*)d_in[8];
    const float* ba       = (const float*)d_in[9];
    const float* W1       = (const float*)d_in[10];
    const float* b1       = (const float*)d_in[11];
    const float* W2       = (const float*)d_in[12];
    const float* b2       = (const float*)d_in[13];
    const float* wddg     = (const float*)d_in[14];
    const float* bddg     = (const float*)d_in[15];
    float* out = (float*)d_out;

    k_prep<<<PREP_BLOCKS, 256>>>(Wf, Wa, W1, W2, etab, E_idx, mut_pos,
                                 bf, ba, b1, b2, wddg, bddg);
    k_conv<<<dim3(32, KSZ, NCH), 512>>>();
    k_softmax<<<dim3(BB, 4), 128>>>();
    k_mlp1<<<dim3(30, NCH), 512>>>();
    k_mlp2<<<dim3(31, NCH), 512>>>(b1, wddg);
    k_score<<<dim3(NSEQ, BB), 128>>>(sortcery, seqs, mut_pos, out);
}